// round 17
// baseline (speedup 1.0000x reference)
#include <cuda_runtime.h>
#include <cuda_fp16.h>
#include <math.h>
#include <stdint.h>

// ---------------------------------------------------------------------------
// Problem constants
// ---------------------------------------------------------------------------
#define BD      2
#define LSEQ    2048
#define DMODEL  2048
#define NH      16
#define HD      128
#define ROWS    (BD * LSEQ)      // 4096

// ---------------------------------------------------------------------------
// Scratch (device globals -- no allocation allowed)
// ---------------------------------------------------------------------------
__device__ float  g_x2 [ROWS * DMODEL];

__device__ __half g_xn [ROWS * DMODEL];
__device__ __half g_o  [ROWS * DMODEL];
__device__ __half g_ff [(size_t)ROWS * 4 * DMODEL];
__device__ __half g_qf [ROWS * DMODEL];   // [bh][L][HD], q pre-scaled + roped
__device__ __half g_kf [ROWS * DMODEL];   // [bh][L][HD], roped
__device__ __half g_vf [ROWS * DMODEL];   // [bh][L][HD]
__device__ float  g_cos[LSEQ * 64];       // rope tables
__device__ float  g_sin[LSEQ * 64];
// transposed weights [N, K] fp16
__device__ __half g_wqkv[3 * DMODEL * DMODEL];
__device__ __half g_wo  [DMODEL * DMODEL];
__device__ __half g_wp  [(size_t)8 * DMODEL * DMODEL];
__device__ __half g_wff [(size_t)4 * DMODEL * DMODEL];

// ---------------------------------------------------------------------------
// Helpers
// ---------------------------------------------------------------------------
__device__ __forceinline__ uint32_t smem_u32(const void* p) {
    uint32_t a;
    asm("{ .reg .u64 t; cvta.to.shared.u64 t, %1; cvt.u32.u64 %0, t; }"
        : "=r"(a) : "l"(p));
    return a;
}
__device__ __forceinline__ void cp16(uint32_t dst, const void* src) {
    asm volatile("cp.async.cg.shared.global [%0], [%1], 16;" :: "r"(dst), "l"(src));
}
__device__ __forceinline__ void ldsm_x4(uint32_t* r, uint32_t a) {
    asm volatile("ldmatrix.sync.aligned.m8n8.x4.shared.b16 {%0,%1,%2,%3}, [%4];"
        : "=r"(r[0]), "=r"(r[1]), "=r"(r[2]), "=r"(r[3]) : "r"(a));
}
__device__ __forceinline__ void ldsm_x2(uint32_t* r, uint32_t a) {
    asm volatile("ldmatrix.sync.aligned.m8n8.x2.shared.b16 {%0,%1}, [%2];"
        : "=r"(r[0]), "=r"(r[1]) : "r"(a));
}
__device__ __forceinline__ void ldsm_x2t(uint32_t* r, uint32_t a) {
    asm volatile("ldmatrix.sync.aligned.m8n8.x2.trans.shared.b16 {%0,%1}, [%2];"
        : "=r"(r[0]), "=r"(r[1]) : "r"(a));
}
__device__ __forceinline__ void mma_f32(float* d, const uint32_t* a, const uint32_t* b) {
    asm volatile("mma.sync.aligned.m16n8k16.row.col.f32.f16.f16.f32 "
        "{%0,%1,%2,%3}, {%4,%5,%6,%7}, {%8,%9}, {%0,%1,%2,%3};"
        : "+f"(d[0]), "+f"(d[1]), "+f"(d[2]), "+f"(d[3])
        : "r"(a[0]), "r"(a[1]), "r"(a[2]), "r"(a[3]), "r"(b[0]), "r"(b[1]));
}
__device__ __forceinline__ uint32_t pack2h(float a, float b) {
    __half2 h = __floats2half2_rn(a, b);
    return *(uint32_t*)&h;
}
__device__ __forceinline__ float silu_f(float x) {
    return x / (1.f + __expf(-x));
}

// ---------------------------------------------------------------------------
// fp16 mma GEMM: C[M,N] = A[M,K] @ B[N,K]^T + bias (+res)
// OUTH=0: fp32 C (+ optional fp32 res). OUTH=1: fp16 C, no res.
// CTA 128x128, 16 warps, warp tile 32x32, 512 threads, K-chunk 64,
// 4-stage cp.async (144KB smem). Pitch 144B: ldmatrix conflict-free.
// ---------------------------------------------------------------------------
#define GK       64
#define APITCH_B 144
#define COMP_B   18432            // 128 * 144
#define STAGE_B  36864            // A + B
#define NSTAGE   4
#define GSMEM    (NSTAGE * STAGE_B)   // 147456

__device__ __forceinline__ void g_load_chunk(
    uint32_t st, int c, int tid,
    const __half* __restrict__ A, const __half* __restrict__ B,
    int K, int m0, int n0)
{
    const int k0 = c * GK;
    #pragma unroll
    for (int i = 0; i < 2; i++) {
        int e = tid + (i << 9);          // 0..1023
        int r = e >> 3, cc = e & 7;      // row, 16B chunk in 128B row
        uint32_t so = (uint32_t)(r * APITCH_B + cc * 16);
        cp16(st + so,          A + (size_t)(m0 + r) * K + k0 + cc * 8);
        cp16(st + COMP_B + so, B + (size_t)(n0 + r) * K + k0 + cc * 8);
    }
    asm volatile("cp.async.commit_group;" ::: "memory");
}

template<int OUTH>
__global__ void __launch_bounds__(512)
gemm_kernel(const __half* __restrict__ A, const __half* __restrict__ B,
            const float* __restrict__ bias, const float* __restrict__ res,
            void* __restrict__ Cv, int K, int N)
{
    extern __shared__ __align__(16) char sm_[];
    const uint32_t sb = smem_u32(sm_);
    const int tid  = threadIdx.x;
    const int lane = tid & 31;
    const int wid  = tid >> 5;
    const int wm   = wid >> 2;
    const int wn   = wid & 3;
    const int m0 = blockIdx.y << 7;
    const int n0 = blockIdx.x << 7;
    const int NC = K / GK;

    float acc[2][4][4];
    #pragma unroll
    for (int i = 0; i < 2; i++)
        #pragma unroll
        for (int j = 0; j < 4; j++)
            #pragma unroll
            for (int q = 0; q < 4; q++) acc[i][j][q] = 0.f;

    g_load_chunk(sb,               0, tid, A, B, K, m0, n0);
    g_load_chunk(sb + STAGE_B,     1, tid, A, B, K, m0, n0);
    g_load_chunk(sb + 2 * STAGE_B, 2, tid, A, B, K, m0, n0);

    const int rowA  = (lane & 7) + ((lane >> 3) & 1) * 8;
    const int kaddA = (lane >> 4) * 16;
    const uint32_t a_ld = (uint32_t)((wm * 32 + rowA) * APITCH_B + kaddA);
    const int rowB  = lane & 7;
    const int kaddB = ((lane >> 3) & 1) * 16;
    const uint32_t b_ld = (uint32_t)((wn * 32 + rowB) * APITCH_B + kaddB);

    for (int c = 0; c < NC; c++) {
        asm volatile("cp.async.wait_group 2;" ::: "memory");
        __syncthreads();

        if (c + 3 < NC)
            g_load_chunk(sb + (uint32_t)((c + 3) & 3) * STAGE_B, c + 3, tid,
                         A, B, K, m0, n0);
        else
            asm volatile("cp.async.commit_group;" ::: "memory");  // keep group count exact

        const uint32_t st = sb + (uint32_t)(c & 3) * STAGE_B;

        #pragma unroll
        for (int kh = 0; kh < 4; kh++) {
            const uint32_t abase = st + a_ld + kh * 32;
            const uint32_t bbase = st + COMP_B + b_ld + kh * 32;

            uint32_t ar[2][4], br[4][2];
            #pragma unroll
            for (int mt = 0; mt < 2; mt++)
                ldsm_x4(ar[mt], abase + mt * (16 * APITCH_B));
            #pragma unroll
            for (int nt = 0; nt < 4; nt++)
                ldsm_x2(br[nt], bbase + nt * (8 * APITCH_B));

            #pragma unroll
            for (int mt = 0; mt < 2; mt++)
                #pragma unroll
                for (int nt = 0; nt < 4; nt++)
                    mma_f32(acc[mt][nt], ar[mt], br[nt]);
        }
    }

    #pragma unroll
    for (int mt = 0; mt < 2; mt++) {
        #pragma unroll
        for (int nt = 0; nt < 4; nt++) {
            const int rg = m0 + wm * 32 + mt * 16 + (lane >> 2);
            const int cg = n0 + wn * 32 + nt * 8 + (lane & 3) * 2;
            float2 bv = *(const float2*)(bias + cg);
            float2 o0, o1;
            o0.x = acc[mt][nt][0] + bv.x;  o0.y = acc[mt][nt][1] + bv.y;
            o1.x = acc[mt][nt][2] + bv.x;  o1.y = acc[mt][nt][3] + bv.y;
            if (OUTH) {
                __half* C = (__half*)Cv;
                __half2 h0, h1;
                h0.x = __float2half_rn(o0.x);  h0.y = __float2half_rn(o0.y);
                h1.x = __float2half_rn(o1.x);  h1.y = __float2half_rn(o1.y);
                *(__half2*)(C + (size_t)rg * N + cg)       = h0;
                *(__half2*)(C + (size_t)(rg + 8) * N + cg) = h1;
            } else {
                float* C = (float*)Cv;
                if (res) {
                    float2 r0 = *(const float2*)(res + (size_t)rg * N + cg);
                    float2 r1 = *(const float2*)(res + (size_t)(rg + 8) * N + cg);
                    o0.x += r0.x; o0.y += r0.y;
                    o1.x += r1.x; o1.y += r1.y;
                }
                *(float2*)(C + (size_t)rg * N + cg)       = o0;
                *(float2*)(C + (size_t)(rg + 8) * N + cg) = o1;
            }
        }
    }
}

// ---------------------------------------------------------------------------
// QKV GEMM with fused bias + RoPE + head-split epilogue.
// N-tile (128) == HD, so each CTA covers exactly one (matrix, head) pair.
// Epilogue: acc+bias -> fp16 smem tile -> rope (table-based) -> Qf/Kf/Vf.
// ---------------------------------------------------------------------------
__global__ void __launch_bounds__(512)
gemm_qkv_kernel(const __half* __restrict__ A, const __half* __restrict__ B,
                const float* __restrict__ bias,
                const float* __restrict__ ctab, const float* __restrict__ stab,
                __half* __restrict__ Qf, __half* __restrict__ Kf,
                __half* __restrict__ Vf, int K, int N)
{
    extern __shared__ __align__(16) char sm_[];
    const uint32_t sb = smem_u32(sm_);
    const int tid  = threadIdx.x;
    const int lane = tid & 31;
    const int wid  = tid >> 5;
    const int wm   = wid >> 2;
    const int wn   = wid & 3;
    const int m0 = blockIdx.y << 7;
    const int n0 = blockIdx.x << 7;
    const int NC = K / GK;

    float acc[2][4][4];
    #pragma unroll
    for (int i = 0; i < 2; i++)
        #pragma unroll
        for (int j = 0; j < 4; j++)
            #pragma unroll
            for (int q = 0; q < 4; q++) acc[i][j][q] = 0.f;

    g_load_chunk(sb,               0, tid, A, B, K, m0, n0);
    g_load_chunk(sb + STAGE_B,     1, tid, A, B, K, m0, n0);
    g_load_chunk(sb + 2 * STAGE_B, 2, tid, A, B, K, m0, n0);

    const int rowA  = (lane & 7) + ((lane >> 3) & 1) * 8;
    const int kaddA = (lane >> 4) * 16;
    const uint32_t a_ld = (uint32_t)((wm * 32 + rowA) * APITCH_B + kaddA);
    const int rowB  = lane & 7;
    const int kaddB = ((lane >> 3) & 1) * 16;
    const uint32_t b_ld = (uint32_t)((wn * 32 + rowB) * APITCH_B + kaddB);

    for (int c = 0; c < NC; c++) {
        asm volatile("cp.async.wait_group 2;" ::: "memory");
        __syncthreads();

        if (c + 3 < NC)
            g_load_chunk(sb + (uint32_t)((c + 3) & 3) * STAGE_B, c + 3, tid,
                         A, B, K, m0, n0);
        else
            asm volatile("cp.async.commit_group;" ::: "memory");

        const uint32_t st = sb + (uint32_t)(c & 3) * STAGE_B;

        #pragma unroll
        for (int kh = 0; kh < 4; kh++) {
            const uint32_t abase = st + a_ld + kh * 32;
            const uint32_t bbase = st + COMP_B + b_ld + kh * 32;

            uint32_t ar[2][4], br[4][2];
            #pragma unroll
            for (int mt = 0; mt < 2; mt++)
                ldsm_x4(ar[mt], abase + mt * (16 * APITCH_B));
            #pragma unroll
            for (int nt = 0; nt < 4; nt++)
                ldsm_x2(br[nt], bbase + nt * (8 * APITCH_B));

            #pragma unroll
            for (int mt = 0; mt < 2; mt++)
                #pragma unroll
                for (int nt = 0; nt < 4; nt++)
                    mma_f32(acc[mt][nt], ar[mt], br[nt]);
        }
    }

    // ---- epilogue: tile -> smem (fp16, pitch 272B), then rope/split ----
    asm volatile("cp.async.wait_group 0;" ::: "memory");
    __syncthreads();

    #pragma unroll
    for (int mt = 0; mt < 2; mt++) {
        #pragma unroll
        for (int nt = 0; nt < 4; nt++) {
            const int rl0 = wm * 32 + mt * 16 + (lane >> 2);   // local row
            const int cl  = wn * 32 + nt * 8 + (lane & 3) * 2; // local col
            float2 bv = *(const float2*)(bias + n0 + cl);
            __half2 h0, h1;
            h0.x = __float2half_rn(acc[mt][nt][0] + bv.x);
            h0.y = __float2half_rn(acc[mt][nt][1] + bv.y);
            h1.x = __float2half_rn(acc[mt][nt][2] + bv.x);
            h1.y = __float2half_rn(acc[mt][nt][3] + bv.y);
            *(__half2*)(sm_ + rl0 * 272 + cl * 2)       = h0;
            *(__half2*)(sm_ + (rl0 + 8) * 272 + cl * 2) = h1;
        }
    }
    __syncthreads();

    const int mat = n0 >> 11;               // 0=q, 1=k, 2=v
    const int hh  = (n0 & 2047) >> 7;       // head
    const int r   = tid >> 2;               // local row 0..127
    const int rg  = m0 + r;
    const int b   = rg >> 11;
    const int l   = rg & 2047;
    const size_t gbase = ((size_t)(b * NH + hh) * LSEQ + l) * HD;
    const __half* srow = (const __half*)(sm_ + r * 272);

    if (mat == 2) {
        const int c0 = (tid & 3) * 32;
        #pragma unroll
        for (int j = 0; j < 32; j += 2)
            *(__half2*)(&Vf[gbase + c0 + j]) = *(const __half2*)(srow + c0 + j);
    } else {
        const float scale = (mat == 0) ? 0.088388347648318447f : 1.0f;
        __half* dst = (mat == 0) ? Qf : Kf;
        const int i0 = (tid & 3) << 4;      // 0,16,32,48
        const float* crow = ctab + l * 64;
        const float* srw  = stab + l * 64;
        #pragma unroll
        for (int j = 0; j < 16; j += 2) {
            int ia = i0 + j, ib = ia + 1;
            float x1a = __half2float(srow[ia]),      x1b = __half2float(srow[ib]);
            float x2a = __half2float(srow[ia + 64]), x2b = __half2float(srow[ib + 64]);
            float ca = crow[ia], sa = srw[ia];
            float cb = crow[ib], sb2 = srw[ib];
            __half2 u, v2;
            u.x  = __float2half_rn((x1a * ca - x2a * sa) * scale);
            u.y  = __float2half_rn((x1b * cb - x2b * sb2) * scale);
            v2.x = __float2half_rn((x2a * ca + x1a * sa) * scale);
            v2.y = __float2half_rn((x2b * cb + x1b * sb2) * scale);
            *(__half2*)(&dst[gbase + ia])      = u;
            *(__half2*)(&dst[gbase + 64 + ia]) = v2;
        }
    }
}

// ---------------------------------------------------------------------------
// RoPE cos/sin tables: [LSEQ][64] fp32
// ---------------------------------------------------------------------------
__global__ void __launch_bounds__(256)
rope_table_kernel(float* __restrict__ ctab, float* __restrict__ stab)
{
    int idx = blockIdx.x * 256 + threadIdx.x;   // [0, 2048*64)
    int i = idx & 63, l = idx >> 6;
    float freq = expf(-(float)i * 0.14391156642875464f);
    float s, c;
    sincosf((float)l * freq, &s, &c);
    ctab[idx] = c;
    stab[idx] = s;
}

// ---------------------------------------------------------------------------
// Fused FFN-up GEMM + SwiGLU, K-chunk 64.
// ---------------------------------------------------------------------------
#define FSTAGE_B (3 * COMP_B)          // 55296
#define FGSMEM   (NSTAGE * FSTAGE_B)   // 221184

__device__ __forceinline__ void f_load_chunk(
    uint32_t st, int c, int tid,
    const __half* __restrict__ A, const __half* __restrict__ Bg,
    const __half* __restrict__ Bv, int K, int m0, int n0)
{
    const int k0 = c * GK;
    #pragma unroll
    for (int i = 0; i < 2; i++) {
        int e = tid + (i << 9);
        int r = e >> 3, cc = e & 7;
        uint32_t so = (uint32_t)(r * APITCH_B + cc * 16);
        size_t goA = (size_t)(m0 + r) * K + k0 + cc * 8;
        size_t goB = (size_t)(n0 + r) * K + k0 + cc * 8;
        cp16(st + so,              A  + goA);
        cp16(st + COMP_B + so,     Bg + goB);
        cp16(st + 2 * COMP_B + so, Bv + goB);
    }
    asm volatile("cp.async.commit_group;" ::: "memory");
}

__global__ void __launch_bounds__(512)
gemm_ffn_kernel(const __half* __restrict__ A, const __half* __restrict__ Wp,
                const float* __restrict__ bp, __half* __restrict__ FF, int K)
{
    extern __shared__ __align__(16) char sm_[];
    const uint32_t sb = smem_u32(sm_);
    const int tid  = threadIdx.x;
    const int lane = tid & 31;
    const int wid  = tid >> 5;
    const int wm   = wid >> 2;
    const int wn   = wid & 3;
    const int m0 = blockIdx.y << 7;
    const int n0 = blockIdx.x << 7;
    const int NC = K / GK;

    const __half* Bg = Wp;
    const __half* Bv = Wp + (size_t)8192 * K;

    float accg[2][4][4], accv[2][4][4];
    #pragma unroll
    for (int i = 0; i < 2; i++)
        #pragma unroll
        for (int j = 0; j < 4; j++)
            #pragma unroll
            for (int q = 0; q < 4; q++) { accg[i][j][q] = 0.f; accv[i][j][q] = 0.f; }

    f_load_chunk(sb,                0, tid, A, Bg, Bv, K, m0, n0);
    f_load_chunk(sb + FSTAGE_B,     1, tid, A, Bg, Bv, K, m0, n0);
    f_load_chunk(sb + 2 * FSTAGE_B, 2, tid, A, Bg, Bv, K, m0, n0);

    const int rowA  = (lane & 7) + ((lane >> 3) & 1) * 8;
    const int kaddA = (lane >> 4) * 16;
    const uint32_t a_ld = (uint32_t)((wm * 32 + rowA) * APITCH_B + kaddA);
    const int rowB  = lane & 7;
    const int kaddB = ((lane >> 3) & 1) * 16;
    const uint32_t b_ld = (uint32_t)((wn * 32 + rowB) * APITCH_B + kaddB);

    for (int c = 0; c < NC; c++) {
        asm volatile("cp.async.wait_group 2;" ::: "memory");
        __syncthreads();

        if (c + 3 < NC)
            f_load_chunk(sb + (uint32_t)((c + 3) & 3) * FSTAGE_B, c + 3, tid,
                         A, Bg, Bv, K, m0, n0);
        else
            asm volatile("cp.async.commit_group;" ::: "memory");

        const uint32_t st = sb + (uint32_t)(c & 3) * FSTAGE_B;

        #pragma unroll
        for (int kh = 0; kh < 4; kh++) {
            const uint32_t abase = st + a_ld + kh * 32;
            const uint32_t gbase = st + COMP_B + b_ld + kh * 32;
            const uint32_t vbase = st + 2 * COMP_B + b_ld + kh * 32;

            uint32_t ar[2][4];
            #pragma unroll
            for (int mt = 0; mt < 2; mt++)
                ldsm_x4(ar[mt], abase + mt * (16 * APITCH_B));

            #pragma unroll
            for (int nt = 0; nt < 4; nt++) {
                uint32_t bg[2], bv_[2];
                ldsm_x2(bg,  gbase + nt * (8 * APITCH_B));
                ldsm_x2(bv_, vbase + nt * (8 * APITCH_B));
                #pragma unroll
                for (int mt = 0; mt < 2; mt++) {
                    mma_f32(accg[mt][nt], ar[mt], bg);
                    mma_f32(accv[mt][nt], ar[mt], bv_);
                }
            }
        }
    }

    #pragma unroll
    for (int mt = 0; mt < 2; mt++) {
        #pragma unroll
        for (int nt = 0; nt < 4; nt++) {
            const int rg = m0 + wm * 32 + mt * 16 + (lane >> 2);
            const int cg = n0 + wn * 32 + nt * 8 + (lane & 3) * 2;
            float2 bg2 = *(const float2*)(bp + cg);
            float2 bv2 = *(const float2*)(bp + 8192 + cg);
            float f00 = silu_f(accg[mt][nt][0] + bg2.x) * (accv[mt][nt][0] + bv2.x);
            float f01 = silu_f(accg[mt][nt][1] + bg2.y) * (accv[mt][nt][1] + bv2.y);
            float f10 = silu_f(accg[mt][nt][2] + bg2.x) * (accv[mt][nt][2] + bv2.x);
            float f11 = silu_f(accg[mt][nt][3] + bg2.y) * (accv[mt][nt][3] + bv2.y);
            __half2 h0, h1;
            h0.x = __float2half_rn(f00);  h0.y = __float2half_rn(f01);
            h1.x = __float2half_rn(f10);  h1.y = __float2half_rn(f11);
            *(__half2*)(FF + (size_t)rg * 8192 + cg)       = h0;
            *(__half2*)(FF + (size_t)(rg + 8) * 8192 + cg) = h1;
        }
    }
}

// ---------------------------------------------------------------------------
// Weight transpose + fp16 round: 64k x 32n tiles, 16B vectorized stores
// ---------------------------------------------------------------------------
__global__ void __launch_bounds__(256)
transp_half(const float* __restrict__ W, __half* __restrict__ Th, int Kd, int Nd)
{
    __shared__ float t[64][33];
    const int n0 = blockIdx.x * 32, k0 = blockIdx.y * 64;
    const int tx = threadIdx.x & 31, ty = threadIdx.x >> 5;
    #pragma unroll
    for (int i = 0; i < 8; i++) {
        int kk = ty + i * 8;
        t[kk][tx] = W[(size_t)(k0 + kk) * Nd + n0 + tx];
    }
    __syncthreads();
    const int nn = threadIdx.x >> 3;          // 0..31
    const int j  = (threadIdx.x & 7) * 8;     // 0..56
    __half hv[8];
    #pragma unroll
    for (int p = 0; p < 8; p++) hv[p] = __float2half_rn(t[j + p][nn]);
    *(uint4*)(Th + (size_t)(n0 + nn) * Kd + k0 + j) = *(uint4*)hv;
}

// ---------------------------------------------------------------------------
// RMSNorm -> fp16
// ---------------------------------------------------------------------------
__global__ void __launch_bounds__(256)
rmsnorm_half(const float* __restrict__ in, const float* __restrict__ g,
             __half* __restrict__ outh)
{
    __shared__ float red[8];
    const int row = blockIdx.x;
    const int tid = threadIdx.x;
    const float4* inr = (const float4*)(in + (size_t)row * DMODEL);
    float4 v0 = inr[tid];
    float4 v1 = inr[tid + 256];
    float ss = v0.x*v0.x + v0.y*v0.y + v0.z*v0.z + v0.w*v0.w
             + v1.x*v1.x + v1.y*v1.y + v1.z*v1.z + v1.w*v1.w;
    #pragma unroll
    for (int o = 16; o; o >>= 1) ss += __shfl_xor_sync(0xffffffffu, ss, o);
    if ((tid & 31) == 0) red[tid >> 5] = ss;
    __syncthreads();
    float tot = red[0]+red[1]+red[2]+red[3]+red[4]+red[5]+red[6]+red[7];
    float rs = rsqrtf(tot * (1.0f / DMODEL) + 1e-8f);

    const float4* gr = (const float4*)g;
    float4 ga = gr[tid], gb = gr[tid + 256];
    __half2* oh2 = (__half2*)(outh + (size_t)row * DMODEL);
    float y[8] = { v0.x*rs*ga.x, v0.y*rs*ga.y, v0.z*rs*ga.z, v0.w*rs*ga.w,
                   v1.x*rs*gb.x, v1.y*rs*gb.y, v1.z*rs*gb.z, v1.w*rs*gb.w };
    #pragma unroll
    for (int p = 0; p < 4; p++) {
        __half2 hh;
        hh.x = __float2half_rn(y[p*2]);
        hh.y = __float2half_rn(y[p*2+1]);
        int base = (p < 2) ? (tid*2 + p) : ((tid+256)*2 + (p-2));
        oh2[base] = hh;
    }
}

// ---------------------------------------------------------------------------
// Flash attention v2 (fp16 mma, causal), Q-tile 128 rows, 8 warps (256 thr).
// Double-buffered K/V pipeline. smem: Q 128x272 + 2x(K,V) 64x272 = 104448 B.
// ---------------------------------------------------------------------------
#define FA_PITCH 272
#define FAQ_TILE (128 * FA_PITCH)    // 34816
#define FAK_TILE (64 * FA_PITCH)     // 17408
#define FA_SMEM  (FAQ_TILE + 4 * FAK_TILE)  // 104448

__global__ void __launch_bounds__(256)
attn_mma(const __half* __restrict__ Qf, const __half* __restrict__ Kf,
         const __half* __restrict__ Vf, __half* __restrict__ O)
{
    extern __shared__ __align__(16) char fsm[];
    const uint32_t sQ  = smem_u32(fsm);
    const uint32_t sKV = sQ + FAQ_TILE;
    const int tid  = threadIdx.x;
    const int lane = tid & 31;
    const int w    = tid >> 5;
    const int bh   = blockIdx.y;
    const int qi   = gridDim.x - 1 - blockIdx.x;
    const int q0   = qi * 128;

    const __half* qb = Qf + (size_t)bh * LSEQ * HD;
    const __half* kb = Kf + (size_t)bh * LSEQ * HD;
    const __half* vb = Vf + (size_t)bh * LSEQ * HD;

    #pragma unroll
    for (int i = 0; i < 8; i++) {
        int e = tid + i * 256;
        int r = e >> 4, cc = e & 15;
        cp16(sQ + r * FA_PITCH + cc * 16, qb + (size_t)(q0 + r) * HD + cc * 8);
    }
    asm volatile("cp.async.commit_group;" ::: "memory");

    #pragma unroll
    for (int i = 0; i < 4; i++) {
        int e = tid + i * 256;
        int r = e >> 4, cc = e & 15;
        size_t go = (size_t)r * HD + cc * 8;
        cp16(sKV + r * FA_PITCH + cc * 16,            kb + go);
        cp16(sKV + FAK_TILE + r * FA_PITCH + cc * 16, vb + go);
    }
    asm volatile("cp.async.commit_group;" ::: "memory");

    const int qg0 = q0 + w * 16 + (lane >> 2);
    const int qg1 = qg0 + 8;

    const uint32_t a_off = (uint32_t)((w * 16 + (lane & 7) + ((lane >> 3) & 1) * 8) * FA_PITCH
                                      + (lane >> 4) * 16);
    const uint32_t b_off = (uint32_t)((lane & 7) * FA_PITCH + ((lane >> 3) & 1) * 16);
    const uint32_t v_off = (uint32_t)((lane & 15) * FA_PITCH);

    float oacc[16][4];
    #pragma unroll
    for (int i = 0; i < 16; i++)
        #pragma unroll
        for (int q = 0; q < 4; q++) oacc[i][q] = 0.f;
    float m0 = -1e30f, m1 = -1e30f, l0 = 0.f, l1 = 0.f;

    const int nk = 2 * qi + 2;
    for (int kt = 0; kt < nk; kt++) {
        if (kt + 1 < nk) {
            const uint32_t dst = sKV + (uint32_t)((kt + 1) & 1) * (2 * FAK_TILE);
            const int kn0 = (kt + 1) * 64;
            #pragma unroll
            for (int i = 0; i < 4; i++) {
                int e = tid + i * 256;
                int r = e >> 4, cc = e & 15;
                size_t go = (size_t)(kn0 + r) * HD + cc * 8;
                cp16(dst + r * FA_PITCH + cc * 16,            kb + go);
                cp16(dst + FAK_TILE + r * FA_PITCH + cc * 16, vb + go);
            }
            asm volatile("cp.async.commit_group;" ::: "memory");
            asm volatile("cp.async.wait_group 1;" ::: "memory");
        } else {
            asm volatile("cp.async.wait_group 0;" ::: "memory");
        }
        __syncthreads();

        const uint32_t sK = sKV + (uint32_t)(kt & 1) * (2 * FAK_TILE);
        const uint32_t sV = sK + FAK_TILE;
        const int k0 = kt * 64;

        float sacc[8][4];
        #pragma unroll
        for (int nt = 0; nt < 8; nt++)
            #pragma unroll
            for (int q = 0; q < 4; q++) sacc[nt][q] = 0.f;

        #pragma unroll
        for (int ks = 0; ks < 8; ks++) {
            uint32_t aq[4];
            ldsm_x4(aq, sQ + a_off + ks * 32);
            #pragma unroll
            for (int nt = 0; nt < 8; nt++) {
                uint32_t bk[2];
                ldsm_x2(bk, sK + nt * (8 * FA_PITCH) + b_off + ks * 32);
                mma_f32(sacc[nt], aq, bk);
            }
        }

        if (k0 + 63 > q0 + w * 16) {
            #pragma unroll
            for (int nt = 0; nt < 8; nt++) {
                int jg = k0 + nt * 8 + (lane & 3) * 2;
                if (jg > qg0)     sacc[nt][0] = -1e30f;
                if (jg + 1 > qg0) sacc[nt][1] = -1e30f;
                if (jg > qg1)     sacc[nt][2] = -1e30f;
                if (jg + 1 > qg1) sacc[nt][3] = -1e30f;
            }
        }

        float tm0 = -1e30f, tm1 = -1e30f;
        #pragma unroll
        for (int nt = 0; nt < 8; nt++) {
            tm0 = fmaxf(tm0, fmaxf(sacc[nt][0], sacc[nt][1]));
            tm1 = fmaxf(tm1, fmaxf(sacc[nt][2], sacc[nt][3]));
        }
        tm0 = fmaxf(tm0, __shfl_xor_sync(0xffffffffu, tm0, 1));
        tm0 = fmaxf(tm0, __shfl_xor_sync(0xffffffffu, tm0, 2));
        tm1 = fmaxf(tm1, __shfl_xor_sync(0xffffffffu, tm1, 1));
        tm1 = fmaxf(tm1, __shfl_xor_sync(0xffffffffu, tm1, 2));

        float mn0 = fmaxf(m0, tm0), mn1 = fmaxf(m1, tm1);
        float c0 = __expf(m0 - mn0), c1 = __expf(m1 - mn1);
        float ps0 = 0.f, ps1 = 0.f;
        #pragma unroll
        for (int nt = 0; nt < 8; nt++) {
            sacc[nt][0] = __expf(sacc[nt][0] - mn0);
            sacc[nt][1] = __expf(sacc[nt][1] - mn0);
            sacc[nt][2] = __expf(sacc[nt][2] - mn1);
            sacc[nt][3] = __expf(sacc[nt][3] - mn1);
            ps0 += sacc[nt][0] + sacc[nt][1];
            ps1 += sacc[nt][2] + sacc[nt][3];
        }
        ps0 += __shfl_xor_sync(0xffffffffu, ps0, 1);
        ps0 += __shfl_xor_sync(0xffffffffu, ps0, 2);
        ps1 += __shfl_xor_sync(0xffffffffu, ps1, 1);
        ps1 += __shfl_xor_sync(0xffffffffu, ps1, 2);
        l0 = l0 * c0 + ps0;  m0 = mn0;
        l1 = l1 * c1 + ps1;  m1 = mn1;
        #pragma unroll
        for (int nt2 = 0; nt2 < 16; nt2++) {
            oacc[nt2][0] *= c0;  oacc[nt2][1] *= c0;
            oacc[nt2][2] *= c1;  oacc[nt2][3] *= c1;
        }

        uint32_t pa[4][4];
        #pragma unroll
        for (int kp = 0; kp < 4; kp++) {
            pa[kp][0] = pack2h(sacc[2*kp][0],   sacc[2*kp][1]);
            pa[kp][1] = pack2h(sacc[2*kp][2],   sacc[2*kp][3]);
            pa[kp][2] = pack2h(sacc[2*kp+1][0], sacc[2*kp+1][1]);
            pa[kp][3] = pack2h(sacc[2*kp+1][2], sacc[2*kp+1][3]);
        }

        #pragma unroll
        for (int kp = 0; kp < 4; kp++) {
            const uint32_t vb_ = sV + (uint32_t)(kp * 16) * FA_PITCH + v_off;
            #pragma unroll
            for (int nt2 = 0; nt2 < 16; nt2++) {
                uint32_t bv[2];
                ldsm_x2t(bv, vb_ + nt2 * 16);
                mma_f32(oacc[nt2], pa[kp], bv);
            }
        }
        __syncthreads();
    }

    float i0 = 1.f / l0, i1 = 1.f / l1;
    const int b  = bh >> 4;
    const int hh = bh & 15;
    size_t row0 = (size_t)b * LSEQ + qg0;
    size_t row1 = row0 + 8;
    #pragma unroll
    for (int nt2 = 0; nt2 < 16; nt2++) {
        int col = hh * HD + nt2 * 8 + (lane & 3) * 2;
        __half2 h0, h1;
        h0.x = __float2half_rn(oacc[nt2][0] * i0);
        h0.y = __float2half_rn(oacc[nt2][1] * i0);
        h1.x = __float2half_rn(oacc[nt2][2] * i1);
        h1.y = __float2half_rn(oacc[nt2][3] * i1);
        *(__half2*)(O + row0 * DMODEL + col) = h0;
        *(__half2*)(O + row1 * DMODEL + col) = h1;
    }
}

// ---------------------------------------------------------------------------
// Host launcher
// ---------------------------------------------------------------------------
extern "C" void kernel_launch(void* const* d_in, const int* in_sizes, int n_in,
                              void* d_out, int out_size)
{
    const float* x    = (const float*)d_in[0];
    const float* Wqkv = (const float*)d_in[1];
    const float* bqkv = (const float*)d_in[2];
    const float* Wo   = (const float*)d_in[3];
    const float* bo   = (const float*)d_in[4];
    const float* g1   = (const float*)d_in[5];
    const float* g2   = (const float*)d_in[6];
    const float* Wp   = (const float*)d_in[7];
    const float* bp   = (const float*)d_in[8];
    const float* Wff  = (const float*)d_in[9];
    const float* bff  = (const float*)d_in[10];
    float* out = (float*)d_out;

    float *p_x2, *p_cos, *p_sin;
    __half *p_xn, *p_o, *p_ff, *p_qf, *p_kf, *p_vf;
    __half *p_wqkv, *p_wo, *p_wp, *p_wff;
    cudaGetSymbolAddress((void**)&p_x2,   g_x2);
    cudaGetSymbolAddress((void**)&p_xn,   g_xn);
    cudaGetSymbolAddress((void**)&p_o,    g_o);
    cudaGetSymbolAddress((void**)&p_ff,   g_ff);
    cudaGetSymbolAddress((void**)&p_qf,   g_qf);
    cudaGetSymbolAddress((void**)&p_kf,   g_kf);
    cudaGetSymbolAddress((void**)&p_vf,   g_vf);
    cudaGetSymbolAddress((void**)&p_cos,  g_cos);
    cudaGetSymbolAddress((void**)&p_sin,  g_sin);
    cudaGetSymbolAddress((void**)&p_wqkv, g_wqkv);
    cudaGetSymbolAddress((void**)&p_wo,   g_wo);
    cudaGetSymbolAddress((void**)&p_wp,   g_wp);
    cudaGetSymbolAddress((void**)&p_wff,  g_wff);

    cudaFuncSetAttribute(attn_mma,        cudaFuncAttributeMaxDynamicSharedMemorySize, FA_SMEM);
    cudaFuncSetAttribute(gemm_kernel<0>,  cudaFuncAttributeMaxDynamicSharedMemorySize, GSMEM);
    cudaFuncSetAttribute(gemm_kernel<1>,  cudaFuncAttributeMaxDynamicSharedMemorySize, GSMEM);
    cudaFuncSetAttribute(gemm_qkv_kernel, cudaFuncAttributeMaxDynamicSharedMemorySize, GSMEM);
    cudaFuncSetAttribute(gemm_ffn_kernel, cudaFuncAttributeMaxDynamicSharedMemorySize, FGSMEM);

    // rope tables + weight transposition (fp16)
    rope_table_kernel<<<(LSEQ * 64) / 256, 256>>>(p_cos, p_sin);
    transp_half<<<dim3(3 * DMODEL / 32, DMODEL / 64), 256>>>(Wqkv, p_wqkv, DMODEL, 3 * DMODEL);
    transp_half<<<dim3(DMODEL / 32, DMODEL / 64), 256>>>(Wo, p_wo, DMODEL, DMODEL);
    transp_half<<<dim3(8 * DMODEL / 32, DMODEL / 64), 256>>>(Wp, p_wp, DMODEL, 8 * DMODEL);
    transp_half<<<dim3(DMODEL / 32, 4 * DMODEL / 64), 256>>>(Wff, p_wff, 4 * DMODEL, DMODEL);

    // 1. pre-norm (-> fp16)
    rmsnorm_half<<<ROWS, 256>>>(x, g1, p_xn);

    // 2+3. QKV projection with fused RoPE/split -> Qf/Kf/Vf
    gemm_qkv_kernel<<<dim3(3 * DMODEL / 128, ROWS / 128), 512, GSMEM>>>(
        p_xn, p_wqkv, bqkv, p_cos, p_sin, p_qf, p_kf, p_vf, DMODEL, 3 * DMODEL);

    // 4. causal flash attention (fp16 mma, Q-tile 128, pipelined) -> fp16 O
    attn_mma<<<dim3(LSEQ / 128, BD * NH), 256, FA_SMEM>>>(p_qf, p_kf, p_vf, p_o);

    // 5. output projection + residual (fp32 out)
    gemm_kernel<0><<<dim3(DMODEL / 128, ROWS / 128), 512, GSMEM>>>(
        p_o, p_wo, bo, x, p_x2, DMODEL, DMODEL);

    // 6. second pre-norm (-> fp16)
    rmsnorm_half<<<ROWS, 256>>>(p_x2, g2, p_xn);

    // 7+8. FFN up-projection fused with SwiGLU (-> fp16 ff)
    gemm_ffn_kernel<<<dim3(4 * DMODEL / 128, ROWS / 128), 512, FGSMEM>>>(
        p_xn, p_wp, bp, p_ff, DMODEL);

    // 9. FFN down-projection + residual -> output (fp32)
    gemm_kernel<0><<<dim3(DMODEL / 128, ROWS / 128), 512, GSMEM>>>(
        p_ff, p_wff, bff, p_x2, out, 4 * DMODEL, DMODEL);
}